// round 8
// baseline (speedup 1.0000x reference)
#include <cuda_runtime.h>

#define NN 35
#define NE 1190
#define NB 148
#define ET 16
typedef unsigned long long ull;

// ---------------- device globals ----------------
__device__ __align__(16) float g_h1[NN * 256];
__device__ __align__(16) float g_h2[NN * 256];
__device__ __align__(16) float g_h3[NN * 64];
__device__ __align__(16) float g_msg[NE * 256];
__device__ __align__(16) float g_m3[2][NE * 64];
__device__ __align__(16) float g_w2q[256 * 7 * 256];   // [i][v(6w+b)][o]
__device__ __align__(16) float g_w3q[256 * 7 * 64];
__device__ __align__(16) float g_l2t[256 * 256];
__device__ __align__(16) float g_l3t[256 * 64];
__device__ __align__(16) float g_ea8[NE * 8];
__device__ int   g_perm[NE];
__device__ int   g_offs[NN + 1];
__device__ float g_invd[NN];
__device__ unsigned g_barcnt = 0;
__device__ volatile unsigned g_barphase = 0;

// ---------------- f32x2 helpers ----------------
__device__ __forceinline__ ull fma2(ull a, ull b, ull c) {
    ull d; asm("fma.rn.f32x2 %0, %1, %2, %3;" : "=l"(d) : "l"(a), "l"(b), "l"(c));
    return d;
}
__device__ __forceinline__ ull relu2(ull t) {
    unsigned lo, hi;
    asm("mov.b64 {%0, %1}, %2;" : "=r"(lo), "=r"(hi) : "l"(t));
    float fl = fmaxf(__uint_as_float(lo), 0.f);
    float fh = fmaxf(__uint_as_float(hi), 0.f);
    ull r;
    asm("mov.b64 %0, {%1, %2};" : "=l"(r) : "r"(__float_as_uint(fl)), "r"(__float_as_uint(fh)));
    return r;
}
__device__ __forceinline__ float2 u2f(ull t) {
    unsigned lo, hi;
    asm("mov.b64 {%0, %1}, %2;" : "=r"(lo), "=r"(hi) : "l"(t));
    return make_float2(__uint_as_float(lo), __uint_as_float(hi));
}
__device__ __forceinline__ ull dup2(float v) {
    ull r; asm("mov.b64 %0, {%1, %1};" : "=l"(r) : "r"(__float_as_uint(v)));
    return r;
}

// ---------------- shared memory ----------------
struct MsgSm {
    __align__(16) ull ea[ET * 8];                  // duplicated edge attrs
    __align__(16) union {
        ull    xs[ET * 256];                       // duplicated source features
        float2 red[8 * 32 * (ET + 1)];             // aliased after compute
    } u;
    int src[ET];
};
struct AggSm {
    int    perm[NE];
    int    off[NN + 1];
    float  inv[NN];
    float  hn[256];
    float2 sred[8][64];
};
union SmU { MsgSm m; AggSm a; char setup[9216]; };

// setup tile layout (512-thread blocks)
#define B_L1   75
#define B_P2   (B_L1 + 128)
#define B_P3   (B_P2 + 32)
#define B_T2   (B_P3 + 32)
#define B_T3   (B_T2 + 8)
#define B_EA   (B_T3 + 2)
#define B_ALL  (B_EA + 1)

// ---------------- grid barrier (replay-safe, monotonic) ----------------
__device__ __forceinline__ void gridsync(unsigned target) {
    __threadfence();
    __syncthreads();
    if (threadIdx.x == 0) {
        unsigned nb = gridDim.x;
        unsigned old = atomicAdd(&g_barcnt, 1u);
        if (old == nb - 1) {
            atomicExch(&g_barcnt, 0u);
            __threadfence();
            g_barphase = target;
        } else {
            while ((int)(g_barphase - target) < 0) __nanosleep(64);
            __threadfence();
        }
    }
    __syncthreads();
}

// ---------------- msg subtile: ET edges x 64 o, 16-warp i-split ----------------
template <int L>
__device__ __forceinline__ void msg_tile(SmU* sm, const int* __restrict__ eidx,
                                         int e0, int oc, int ih) {
    constexpr int OTOT = (L == 3) ? 64 : 256;
    constexpr int OP = OTOT / 2;
    constexpr int IW = (L == 3) ? 128 : 256;
    constexpr int IPW = IW / 16;                   // i per warp
    constexpr int NITB = IPW / 2;
    const float* __restrict__ wq  = (L == 3) ? g_w3q : g_w2q;
    const float* __restrict__ hin = (L == 3) ? g_h2 : g_h1;
    float* __restrict__ msgout    = (L == 3) ? &g_m3[ih][0] : g_msg;

    int tid = threadIdx.x, lane = tid & 31, w = tid >> 5;
    int op = (oc >> 1) + lane;

    // ---- load tile inputs ----
    if (tid < ET) {
        int ee = e0 + tid; if (ee >= NE) ee = NE - 1;
        sm->m.src[tid] = eidx[ee];
    }
    __syncthreads();
    if (tid < ET * 8) {
        int e = tid >> 3, ee = e0 + e; if (ee >= NE) ee = NE - 1;
        sm->m.ea[tid] = dup2(g_ea8[ee * 8 + (tid & 7)]);
    }
    for (int idx = tid; idx < ET * IW; idx += 512) {
        int e = idx / IW, c = ih * 128 + (idx % IW);
        sm->m.u.xs[idx] = dup2(hin[sm->m.src[e] * 256 + c]);
    }
    __syncthreads();

    const ull* __restrict__ wq2 = (const ull*)wq;
    const ulonglong2* __restrict__ xs2 = (const ulonglong2*)sm->m.u.xs;
    const ulonglong2* __restrict__ ea2 = (const ulonglong2*)sm->m.ea;

    ull acc[ET];
#pragma unroll
    for (int e = 0; e < ET; e++) acc[e] = 0ull;

    ull wA[14], wB[14];
    const int igw = ih * 128 + w * IPW;            // warp's first global i

    {   // prefetch itb 0
        size_t b0 = (size_t)(igw * 7) * OP + op;
#pragma unroll
        for (int v = 0; v < 7; v++) { wA[v] = wq2[b0 + v * OP]; wA[7 + v] = wq2[b0 + (7 + v) * OP]; }
    }

#pragma unroll 1
    for (int itb = 0; itb < NITB; itb += 2) {
        {   // prefetch itb+1
            size_t b0 = (size_t)((igw + (itb + 1) * 2) * 7) * OP + op;
#pragma unroll
            for (int v = 0; v < 7; v++) { wB[v] = wq2[b0 + v * OP]; wB[7 + v] = wq2[b0 + (7 + v) * OP]; }
        }
        {   // compute itb (wA)
            int iloc = w * IPW + itb * 2;
#pragma unroll
            for (int e = 0; e < ET; e++) {
                ulonglong2 A01 = ea2[e * 4 + 0], A23 = ea2[e * 4 + 1], A45 = ea2[e * 4 + 2];
                ulonglong2 X = xs2[(e * IW + iloc) >> 1];
                ull t0 = fma2(wA[0], A01.x, wA[6]);
                t0 = fma2(wA[1], A01.y, t0); t0 = fma2(wA[2], A23.x, t0);
                t0 = fma2(wA[3], A23.y, t0); t0 = fma2(wA[4], A45.x, t0);
                t0 = fma2(wA[5], A45.y, t0);
                acc[e] = fma2(X.x, relu2(t0), acc[e]);
                ull t1 = fma2(wA[7], A01.x, wA[13]);
                t1 = fma2(wA[8], A01.y, t1); t1 = fma2(wA[9], A23.x, t1);
                t1 = fma2(wA[10], A23.y, t1); t1 = fma2(wA[11], A45.x, t1);
                t1 = fma2(wA[12], A45.y, t1);
                acc[e] = fma2(X.y, relu2(t1), acc[e]);
            }
        }
        if (itb + 2 < NITB) {   // prefetch itb+2
            size_t b0 = (size_t)((igw + (itb + 2) * 2) * 7) * OP + op;
#pragma unroll
            for (int v = 0; v < 7; v++) { wA[v] = wq2[b0 + v * OP]; wA[7 + v] = wq2[b0 + (7 + v) * OP]; }
        }
        {   // compute itb+1 (wB)
            int iloc = w * IPW + (itb + 1) * 2;
#pragma unroll
            for (int e = 0; e < ET; e++) {
                ulonglong2 A01 = ea2[e * 4 + 0], A23 = ea2[e * 4 + 1], A45 = ea2[e * 4 + 2];
                ulonglong2 X = xs2[(e * IW + iloc) >> 1];
                ull t0 = fma2(wB[0], A01.x, wB[6]);
                t0 = fma2(wB[1], A01.y, t0); t0 = fma2(wB[2], A23.x, t0);
                t0 = fma2(wB[3], A23.y, t0); t0 = fma2(wB[4], A45.x, t0);
                t0 = fma2(wB[5], A45.y, t0);
                acc[e] = fma2(X.x, relu2(t0), acc[e]);
                ull t1 = fma2(wB[7], A01.x, wB[13]);
                t1 = fma2(wB[8], A01.y, t1); t1 = fma2(wB[9], A23.x, t1);
                t1 = fma2(wB[10], A23.y, t1); t1 = fma2(wB[11], A45.x, t1);
                t1 = fma2(wB[12], A45.y, t1);
                acc[e] = fma2(X.y, relu2(t1), acc[e]);
            }
        }
    }

    // ---- 2-step reduction (red aliases xs; xs reads done) ----
    __syncthreads();
    if (w < 8) {
#pragma unroll
        for (int e = 0; e < ET; e++) sm->m.u.red[(w * 32 + lane) * (ET + 1) + e] = u2f(acc[e]);
    }
    __syncthreads();
    if (w >= 8) {
#pragma unroll
        for (int e = 0; e < ET; e++) {
            float2 f = u2f(acc[e]);
            float2* r = &sm->m.u.red[((w - 8) * 32 + lane) * (ET + 1) + e];
            r->x += f.x; r->y += f.y;
        }
    }
    __syncthreads();
    {
        int opair = tid & 31, e = tid >> 5;        // 512 outputs exactly
        int ee = e0 + e;
        if (ee < NE) {
            float2 s = make_float2(0.f, 0.f);
#pragma unroll
            for (int ww = 0; ww < 8; ww++) {
                float2 p = sm->m.u.red[(ww * 32 + opair) * (ET + 1) + e];
                s.x += p.x; s.y += p.y;
            }
            *(float2*)(msgout + ee * OTOT + oc + 2 * opair) = s;
        }
    }
    __syncthreads();
}

__device__ __forceinline__ void load_csr(SmU* sm) {
    int tid = threadIdx.x;
    for (int j = tid; j < NE; j += 512) sm->a.perm[j] = g_perm[j];
    if (tid <= NN) sm->a.off[tid] = g_offs[tid];
    if (tid < NN) sm->a.inv[tid] = g_invd[tid];
    __syncthreads();
}

// batched gather: 8 groups, stride-8 over edge list
__device__ __forceinline__ float gather8(SmU* sm, const float* __restrict__ base,
                                         int stride, int o, int j0, int j1, int g) {
    float acc = 0.f;
#pragma unroll
    for (int k = 0; k < 8; k++) {
        int j = j0 + g + 8 * k;
        if (j < j1) acc += base[sm->a.perm[j] * stride + o];
    }
    for (int j = j0 + g + 64; j < j1; j += 8) acc += base[sm->a.perm[j] * stride + o];
    return acc;
}

// ---------------- the single persistent kernel ----------------
__global__ void __launch_bounds__(512, 1) k_all(
    const float* __restrict__ x,  const float* __restrict__ ea,
    const int* __restrict__ eidx,
    const float* __restrict__ n1w, const float* __restrict__ n1b,
    const float* __restrict__ l1w, const float* __restrict__ b1,
    const float* __restrict__ n2w, const float* __restrict__ n2b,
    const float* __restrict__ b2,
    const float* __restrict__ n3w, const float* __restrict__ n3b,
    const float* __restrict__ b3,
    const float* __restrict__ l2w, const float* __restrict__ l3w,
    float* __restrict__ out)
{
    __shared__ SmU sm;
    __shared__ unsigned s_base;
    int tid = threadIdx.x, bid = blockIdx.x;
    int lane = tid & 31, w = tid >> 5;

    if (tid == 0) s_base = g_barphase;
    __syncthreads();
    unsigned base = s_base;

    // ================= phase 0: setup =================
    for (int b = bid; b < B_ALL; b += NB) {
        if (b < B_L1) {                                  // layer-1 messages (c_in=1)
            int half = tid >> 8, o = tid & 255;
            int e0 = b * 16 + half * 8;
            float wv[6];
#pragma unroll
            for (int v = 0; v < 6; v++) wv[v] = n1w[o * 6 + v];
            float bb = n1b[o];
#pragma unroll
            for (int k = 0; k < 8; k++) {
                int e = e0 + k;
                if (e < NE) {
                    float t = bb;
#pragma unroll
                    for (int v = 0; v < 6; v++) t = fmaf(wv[v], ea[e * 6 + v], t);
                    g_msg[e * 256 + o] = x[eidx[e]] * fmaxf(t, 0.f);
                }
            }
        } else if (b < B_P2) {                           // pack nn2 (2 i per block)
            int i = (b - B_L1) * 2 + (tid >> 8), o = tid & 255, io = i * 256 + o;
#pragma unroll
            for (int v = 0; v < 6; v++) g_w2q[(i * 7 + v) * 256 + o] = n2w[io * 6 + v];
            g_w2q[(i * 7 + 6) * 256 + o] = n2b[io];
        } else if (b < B_P3) {                           // pack nn3 (8 i per block)
            int i = (b - B_P2) * 8 + (tid >> 6), o = tid & 63, io = i * 64 + o;
#pragma unroll
            for (int v = 0; v < 6; v++) g_w3q[(i * 7 + v) * 64 + o] = n3w[io * 6 + v];
            g_w3q[(i * 7 + 6) * 64 + o] = n3b[io];
        } else if (b < B_T2) {                           // transpose lin2 (2 tiles/block)
            int sel = tid >> 8, t2 = tid & 255;
            float* tile = (float*)sm.setup + sel * 1056;
            int rt = (b - B_P3) * 2 + sel;
            int bo = (rt & 7) * 32, bi = (rt >> 3) * 32;
            int tx = t2 & 31, ty = t2 >> 5;
#pragma unroll
            for (int r = 0; r < 4; r++)
                tile[(ty + r * 8) * 33 + tx] = l2w[(bo + ty + r * 8) * 256 + bi + tx];
            __syncthreads();
#pragma unroll
            for (int r = 0; r < 4; r++)
                g_l2t[(bi + ty + r * 8) * 256 + bo + tx] = tile[tx * 33 + ty + r * 8];
        } else if (b < B_T3) {                           // transpose lin3 (2 tiles/block)
            int sel = tid >> 8, t2 = tid & 255;
            float* tile = (float*)sm.setup + sel * 1056;
            int rt = (b - B_T2) * 2 + sel;
            int bo = (rt & 1) * 32, bi = (rt >> 1) * 32;
            int tx = t2 & 31, ty = t2 >> 5;
#pragma unroll
            for (int r = 0; r < 4; r++)
                tile[(ty + r * 8) * 33 + tx] = l3w[(bo + ty + r * 8) * 256 + bi + tx];
            __syncthreads();
#pragma unroll
            for (int r = 0; r < 4; r++)
                g_l3t[(bi + ty + r * 8) * 64 + bo + tx] = tile[tx * 33 + ty + r * 8];
        } else if (b < B_EA) {                           // pad edge attrs
            int rb = b - B_T3;
            for (int idx = rb * 512 + tid; idx < NE * 8; idx += 2 * 512) {
                int e = idx >> 3, v = idx & 7;
                g_ea8[idx] = (v < 6) ? ea[e * 6 + v] : 0.f;
            }
        } else {                                         // deterministic CSR by dst
            int* s_dst = (int*)sm.setup;
            int* s_cnt = s_dst + NE;
            int* s_off = s_cnt + 7 * NN;
            for (int e = tid; e < NE; e += 512) s_dst[e] = eidx[NE + e];
            __syncthreads();
            if (tid < 7 * NN) {
                int c = tid / NN, n = tid % NN;
                int lo = c * 170, cnt = 0;
                for (int e = lo; e < lo + 170; e++) cnt += (s_dst[e] == n);
                s_cnt[c * NN + n] = cnt;
            }
            __syncthreads();
            if (tid == 0) {
                int off = 0;
                for (int n = 0; n < NN; n++) {
                    s_off[n] = off;
                    for (int c = 0; c < 7; c++) {
                        int t = s_cnt[c * NN + n];
                        s_cnt[c * NN + n] = off;
                        off += t;
                    }
                }
                s_off[NN] = off;
            }
            __syncthreads();
            if (tid < 7 * NN) {
                int c = tid / NN, n = tid % NN;
                int lo = c * 170, p = s_cnt[c * NN + n];
                for (int e = lo; e < lo + 170; e++)
                    if (s_dst[e] == n) g_perm[p++] = e;
            }
            if (tid <= NN) g_offs[tid] = s_off[tid];
            if (tid < NN) g_invd[tid] = 1.0f / (float)max(s_off[tid + 1] - s_off[tid], 1);
        }
        __syncthreads();
    }
    gridsync(base + 1);

    // ================= phase 1: agg1 (140 tasks) =================
    load_csr(&sm);
    for (int t = bid; t < NN * 4; t += NB) {
        int n = t % NN, oc = (t / NN) * 64;
        int o64 = tid & 63, g = tid >> 6, o = oc + o64;
        int j0 = sm.a.off[n], j1 = sm.a.off[n + 1];
        float acc = gather8(&sm, g_msg, 256, o, j0, j1, g);
        sm.a.sred[g][o64] = make_float2(acc, 0.f);
        __syncthreads();
        if (tid < 64) {
            int oo = oc + tid;
            float tot = 0.f;
#pragma unroll
            for (int gg = 0; gg < 8; gg++) tot += sm.a.sred[gg][tid].x;
            g_h1[n * 256 + oo] =
                fmaxf(fmaf(tot, sm.a.inv[n], fmaf(x[n], l1w[oo], b1[oo])), 0.f);
        }
        __syncthreads();
    }
    gridsync(base + 2);

    // ================= phase 2: msg2 (300 subtile tasks) =================
    for (int st = bid; st < 75 * 4; st += NB) {
        int et = st % 75, oc = (st / 75) * 64;
        msg_tile<2>(&sm, eidx, et * ET, oc, 0);
    }
    gridsync(base + 3);

    // ================= phase 3: agg2 (140 tasks) =================
    load_csr(&sm);
    for (int t = bid; t < NN * 4; t += NB) {
        int n = t % NN, oc = (t / NN) * 64;
        int o64 = tid & 63, g = tid >> 6, o = oc + o64;
        if (tid < 256) sm.a.hn[tid] = g_h1[n * 256 + tid];
        __syncthreads();
        int j0 = sm.a.off[n], j1 = sm.a.off[n + 1];
        float macc = gather8(&sm, g_msg, 256, o, j0, j1, g);
        float lin = 0.f;
        int ib = g * 32;
#pragma unroll
        for (int i = 0; i < 32; i++) lin = fmaf(sm.a.hn[ib + i], g_l2t[(ib + i) * 256 + o], lin);
        sm.a.sred[g][o64] = make_float2(macc, lin);
        __syncthreads();
        if (tid < 64) {
            float m = 0.f, l = 0.f;
#pragma unroll
            for (int gg = 0; gg < 8; gg++) { m += sm.a.sred[gg][tid].x; l += sm.a.sred[gg][tid].y; }
            int oo = oc + tid;
            g_h2[n * 256 + oo] = fmaxf(fmaf(m, sm.a.inv[n], l + b2[oo]), 0.f);
        }
        __syncthreads();
    }
    gridsync(base + 4);

    // ================= phase 4: msg3 (150 subtile tasks, i-halves) =================
    for (int st = bid; st < 75 * 2; st += NB) {
        int et = st % 75, ih = st / 75;
        msg_tile<3>(&sm, eidx, et * ET, 0, ih);
    }
    gridsync(base + 5);

    // ================= phase 5: agg3 (35 tasks) =================
    load_csr(&sm);
    for (int t = bid; t < NN; t += NB) {
        int n = t;
        int o64 = tid & 63, g = tid >> 6, o = o64;
        if (tid < 256) sm.a.hn[tid] = g_h2[n * 256 + tid];
        __syncthreads();
        int j0 = sm.a.off[n], j1 = sm.a.off[n + 1];
        float macc = 0.f;
#pragma unroll
        for (int k = 0; k < 8; k++) {
            int j = j0 + g + 8 * k;
            if (j < j1) {
                int e = sm.a.perm[j];
                macc += g_m3[0][e * 64 + o] + g_m3[1][e * 64 + o];
            }
        }
        for (int j = j0 + g + 64; j < j1; j += 8) {
            int e = sm.a.perm[j];
            macc += g_m3[0][e * 64 + o] + g_m3[1][e * 64 + o];
        }
        float lin = 0.f;
        int ib = g * 32;
#pragma unroll
        for (int i = 0; i < 32; i++) lin = fmaf(sm.a.hn[ib + i], g_l3t[(ib + i) * 64 + o], lin);
        sm.a.sred[g][o64] = make_float2(macc, lin);
        __syncthreads();
        if (tid < 64) {
            float m = 0.f, l = 0.f;
#pragma unroll
            for (int gg = 0; gg < 8; gg++) { m += sm.a.sred[gg][tid].x; l += sm.a.sred[gg][tid].y; }
            g_h3[n * 64 + tid] = fmaxf(fmaf(m, sm.a.inv[n], l + b3[tid]), 0.f);
        }
        __syncthreads();
    }
    gridsync(base + 6);

    // ================= phase 6: CBT =================
    {
        for (int p = bid * 16 + w; p < NN * NN; p += NB * 16) {
            int a = p / NN, bb = p % NN;
            float d = fabsf(g_h3[a * 64 + lane] - g_h3[bb * 64 + lane]) +
                      fabsf(g_h3[a * 64 + lane + 32] - g_h3[bb * 64 + lane + 32]);
#pragma unroll
            for (int s = 16; s; s >>= 1) d += __shfl_xor_sync(0xffffffffu, d, s);
            if (lane == 0) out[p] = d;
        }
    }
}

// ---------------- launch ----------------
extern "C" void kernel_launch(void* const* d_in, const int* in_sizes, int n_in,
                              void* d_out, int out_size) {
    const float* x   = (const float*)d_in[0];
    const float* ea  = (const float*)d_in[1];
    const int*   ei  = (const int*)d_in[2];
    const float* n1w = (const float*)d_in[3];
    const float* n1b = (const float*)d_in[4];
    const float* l1w = (const float*)d_in[5];
    const float* b1  = (const float*)d_in[6];
    const float* n2w = (const float*)d_in[7];
    const float* n2b = (const float*)d_in[8];
    const float* l2w = (const float*)d_in[9];
    const float* b2  = (const float*)d_in[10];
    const float* n3w = (const float*)d_in[11];
    const float* n3b = (const float*)d_in[12];
    const float* l3w = (const float*)d_in[13];
    const float* b3  = (const float*)d_in[14];
    float* out = (float*)d_out;
    (void)in_sizes; (void)n_in; (void)out_size;

    k_all<<<NB, 512>>>(x, ea, ei, n1w, n1b, l1w, b1,
                       n2w, n2b, b2, n3w, n3b, b3, l2w, l3w, out);
}

// round 12
// speedup vs baseline: 2.4714x; 2.4714x over previous
#include <cuda_runtime.h>

#define NN 35
#define NE 1190
typedef unsigned long long ull;

// ---------------- scratch ----------------
__device__ __align__(16) float g_h1[NN * 256];
__device__ __align__(16) float g_h2[NN * 256];
__device__ __align__(16) float g_h3[NN * 64];
__device__ __align__(16) float g_msg[NE * 256];
__device__ __align__(16) float g_m3[2][NE * 64];
__device__ __align__(16) float g_w2q[256 * 7 * 256];   // [i][v(6w+b)][o]
__device__ __align__(16) float g_w3q[256 * 7 * 64];
__device__ __align__(16) float g_l2t[256 * 256];
__device__ __align__(16) float g_l3t[256 * 64];
__device__ __align__(16) float g_ea8[NE * 8];
__device__ int   g_perm[NE];
__device__ int   g_offs[NN + 1];
__device__ float g_invd[NN];

// ---------------- f32x2 helpers ----------------
__device__ __forceinline__ ull fma2(ull a, ull b, ull c) {
    ull d; asm("fma.rn.f32x2 %0, %1, %2, %3;" : "=l"(d) : "l"(a), "l"(b), "l"(c));
    return d;
}
__device__ __forceinline__ ull relu2(ull t) {
    unsigned lo, hi;
    asm("mov.b64 {%0, %1}, %2;" : "=r"(lo), "=r"(hi) : "l"(t));
    float fl = fmaxf(__uint_as_float(lo), 0.f);
    float fh = fmaxf(__uint_as_float(hi), 0.f);
    ull r;
    asm("mov.b64 %0, {%1, %2};" : "=l"(r) : "r"(__float_as_uint(fl)), "r"(__float_as_uint(fh)));
    return r;
}
__device__ __forceinline__ float2 u2f(ull t) {
    unsigned lo, hi;
    asm("mov.b64 {%0, %1}, %2;" : "=r"(lo), "=r"(hi) : "l"(t));
    return make_float2(__uint_as_float(lo), __uint_as_float(hi));
}
__device__ __forceinline__ ull dup2(float v) {
    ull r; asm("mov.b64 %0, {%1, %1};" : "=l"(r) : "r"(__float_as_uint(v)));
    return r;
}

// ---------------- fused setup ----------------
#define B_L1   75
#define B_P2   (B_L1 + 256)
#define B_P3   (B_P2 + 16)
#define B_T2   (B_P3 + 64)
#define B_T3   (B_T2 + 16)
#define B_EA   (B_T3 + 5)
#define B_ALL  (B_EA + 1)

__global__ void __launch_bounds__(256) k_setup(
    const float* __restrict__ x,  const float* __restrict__ ea,
    const int* __restrict__ eidx,
    const float* __restrict__ n1w, const float* __restrict__ n1b,
    const float* __restrict__ n2w, const float* __restrict__ n2b,
    const float* __restrict__ n3w, const float* __restrict__ n3b,
    const float* __restrict__ l2w, const float* __restrict__ l3w)
{
    __shared__ __align__(16) char smbuf[8192];
    int b = blockIdx.x, tid = threadIdx.x;

    if (b < B_L1) {                                      // layer-1 messages (c_in=1)
        int e0 = b * 16, o = tid;
        float w[6];
#pragma unroll
        for (int v = 0; v < 6; v++) w[v] = n1w[o * 6 + v];
        float bb = n1b[o];
#pragma unroll
        for (int k = 0; k < 16; k++) {
            int e = e0 + k;
            if (e < NE) {
                float t = bb;
#pragma unroll
                for (int v = 0; v < 6; v++) t = fmaf(w[v], ea[e * 6 + v], t);
                g_msg[e * 256 + o] = x[eidx[e]] * fmaxf(t, 0.f);
            }
        }
    } else if (b < B_P2) {                               // pack nn2
        int i = b - B_L1, o = tid, io = i * 256 + o;
#pragma unroll
        for (int v = 0; v < 6; v++) g_w2q[(i * 7 + v) * 256 + o] = n2w[io * 6 + v];
        g_w2q[(i * 7 + 6) * 256 + o] = n2b[io];
    } else if (b < B_P3) {                               // pack nn3
        int rb = b - B_P2;
#pragma unroll
        for (int r = 0; r < 4; r++) {
            int i = rb * 16 + r * 4 + (tid >> 6), o = tid & 63, io = i * 64 + o;
#pragma unroll
            for (int v = 0; v < 6; v++) g_w3q[(i * 7 + v) * 64 + o] = n3w[io * 6 + v];
            g_w3q[(i * 7 + 6) * 64 + o] = n3b[io];
        }
    } else if (b < B_T2) {                               // transpose lin2
        float* tile = (float*)smbuf;
        int rb = b - B_P3, bo = (rb & 7) * 32, bi = (rb >> 3) * 32;
        int tx = tid & 31, ty = tid >> 5;
#pragma unroll
        for (int r = 0; r < 4; r++)
            tile[(ty + r * 8) * 33 + tx] = l2w[(bo + ty + r * 8) * 256 + bi + tx];
        __syncthreads();
#pragma unroll
        for (int r = 0; r < 4; r++)
            g_l2t[(bi + ty + r * 8) * 256 + bo + tx] = tile[tx * 33 + ty + r * 8];
    } else if (b < B_T3) {                               // transpose lin3
        float* tile = (float*)smbuf;
        int rb = b - B_T2, bo = (rb & 1) * 32, bi = (rb >> 1) * 32;
        int tx = tid & 31, ty = tid >> 5;
#pragma unroll
        for (int r = 0; r < 4; r++)
            tile[(ty + r * 8) * 33 + tx] = l3w[(bo + ty + r * 8) * 256 + bi + tx];
        __syncthreads();
#pragma unroll
        for (int r = 0; r < 4; r++)
            g_l3t[(bi + ty + r * 8) * 64 + bo + tx] = tile[tx * 33 + ty + r * 8];
    } else if (b < B_EA) {                               // pad edge attrs
        int rb = b - B_T3;
        for (int idx = rb * 256 + tid; idx < NE * 8; idx += 5 * 256) {
            int e = idx >> 3, v = idx & 7;
            g_ea8[idx] = (v < 6) ? ea[e * 6 + v] : 0.f;
        }
    } else {                                             // deterministic CSR by dst
        int* s_dst = (int*)smbuf;
        int* s_cnt = s_dst + NE;
        int* s_off = s_cnt + 7 * NN;
        for (int e = tid; e < NE; e += 256) s_dst[e] = eidx[NE + e];
        __syncthreads();
        if (tid < 7 * NN) {
            int c = tid / NN, n = tid % NN;
            int lo = c * 170, cnt = 0;
            for (int e = lo; e < lo + 170; e++) cnt += (s_dst[e] == n);
            s_cnt[c * NN + n] = cnt;
        }
        __syncthreads();
        if (tid == 0) {
            int off = 0;
            for (int n = 0; n < NN; n++) {
                s_off[n] = off;
                for (int c = 0; c < 7; c++) {
                    int t = s_cnt[c * NN + n];
                    s_cnt[c * NN + n] = off;
                    off += t;
                }
            }
            s_off[NN] = off;
        }
        __syncthreads();
        if (tid < 7 * NN) {
            int c = tid / NN, n = tid % NN;
            int lo = c * 170, p = s_cnt[c * NN + n];
            for (int e = lo; e < lo + 170; e++)
                if (s_dst[e] == n) g_perm[p++] = e;
        }
        if (tid <= NN) g_offs[tid] = s_off[tid];
        if (tid < NN) g_invd[tid] = 1.0f / (float)max(s_off[tid + 1] - s_off[tid], 1);
    }
}

// ---------------- batched gather helper ----------------
__device__ __forceinline__ float gather16(const float* __restrict__ base, int stride,
                                          int o, int j0, int j1, int g) {
    float acc = 0.f;
#pragma unroll
    for (int k = 0; k < 16; k++) {
        int j = j0 + g + 4 * k;
        if (j < j1) acc += base[g_perm[j] * stride + o];
    }
    for (int j = j0 + g + 64; j < j1; j += 4) acc += base[g_perm[j] * stride + o];
    return acc;
}

// ---------------- layer-1 aggregate ----------------
__global__ void __launch_bounds__(256) k_agg1(const float* __restrict__ x,
                                              const float* __restrict__ lw,
                                              const float* __restrict__ b) {
    __shared__ float sred[4][64];
    int n = blockIdx.x, o = blockIdx.y * 64 + (threadIdx.x & 63), g = threadIdx.x >> 6;
    int j0 = g_offs[n], j1 = g_offs[n + 1];
    float acc = gather16(g_msg, 256, o, j0, j1, g);
    sred[g][threadIdx.x & 63] = acc;
    __syncthreads();
    if (threadIdx.x < 64) {
        int oo = blockIdx.y * 64 + threadIdx.x;
        float tot = sred[0][threadIdx.x] + sred[1][threadIdx.x] +
                    sred[2][threadIdx.x] + sred[3][threadIdx.x];
        g_h1[n * 256 + oo] = fmaxf(fmaf(tot, g_invd[n], fmaf(x[n], lw[oo], b[oo])), 0.f);
    }
}

// ---------------- heavy message kernel (single-buffer, low-reg) ----------------
// 256 thr = 8 warps; warp w owns i-range IPW; lane owns o-pair; ET edges in acc.
#define ET 16
struct MsgSm {
    union {
        ull    xs[ET * 256];                 // duplicated source features
        float2 red[8 * 32 * (ET + 1)];       // aliased after compute
    };
    ull ea[ET * 8];                          // duplicated edge attrs
    int src[ET];
};

template <int L>
__global__ void __launch_bounds__(256, 2) k_msg(const int* __restrict__ eidx) {
    constexpr int OTOT = (L == 3) ? 64 : 256;
    constexpr int OP = OTOT / 2;
    constexpr int IW = (L == 3) ? 128 : 256;
    constexpr int IPW = IW / 8;              // i per warp (32 / 16)
    constexpr int NITB = IPW / 2;            // i-pair steps per warp
    const float* __restrict__ wq  = (L == 3) ? g_w3q : g_w2q;
    const float* __restrict__ hin = (L == 3) ? g_h2 : g_h1;

    __shared__ MsgSm sm;
    int tid = threadIdx.x, lane = tid & 31, w = tid >> 5;
    int e0 = blockIdx.x * ET;
    int oc = (L == 3) ? 0 : blockIdx.y * 64;
    int ih = (L == 3) ? blockIdx.y : 0;
    int op = (oc >> 1) + lane;
    float* __restrict__ msgout = (L == 3) ? &g_m3[ih][0] : g_msg;

    // ---- load tile inputs ----
    if (tid < ET) {
        int ee = e0 + tid; if (ee >= NE) ee = NE - 1;
        sm.src[tid] = eidx[ee];
    }
    __syncthreads();
    if (tid < ET * 8) {
        int e = tid >> 3, ee = e0 + e; if (ee >= NE) ee = NE - 1;
        sm.ea[tid] = dup2(g_ea8[ee * 8 + (tid & 7)]);
    }
    for (int idx = tid; idx < ET * IW; idx += 256) {
        int e = idx / IW, c = ih * 128 + (idx % IW);
        sm.xs[idx] = dup2(hin[sm.src[e] * 256 + c]);
    }
    __syncthreads();

    const ulonglong2* __restrict__ xs2 = (const ulonglong2*)sm.xs;
    const ulonglong2* __restrict__ ea2 = (const ulonglong2*)sm.ea;

    ull acc[ET];
#pragma unroll
    for (int e = 0; e < ET; e++) acc[e] = 0ull;

    const int i0 = ih * 128 + w * IPW;
    const ull* __restrict__ wp = (const ull*)wq + (size_t)(i0 * 7) * OP + op;

    ull wA[14];
#pragma unroll 1
    for (int itb = 0; itb < NITB; itb++) {
#pragma unroll
        for (int v = 0; v < 14; v++) wA[v] = wp[v * OP];
        wp += 14 * OP;
        int iloc = w * IPW + itb * 2;
#pragma unroll
        for (int e = 0; e < ET; e++) {
            ulonglong2 A01 = ea2[e * 4 + 0], A23 = ea2[e * 4 + 1], A45 = ea2[e * 4 + 2];
            ulonglong2 X = xs2[(e * IW + iloc) >> 1];
            ull t0 = fma2(wA[0], A01.x, wA[6]);
            t0 = fma2(wA[1], A01.y, t0); t0 = fma2(wA[2], A23.x, t0);
            t0 = fma2(wA[3], A23.y, t0); t0 = fma2(wA[4], A45.x, t0);
            t0 = fma2(wA[5], A45.y, t0);
            acc[e] = fma2(X.x, relu2(t0), acc[e]);
            ull t1 = fma2(wA[7], A01.x, wA[13]);
            t1 = fma2(wA[8], A01.y, t1); t1 = fma2(wA[9], A23.x, t1);
            t1 = fma2(wA[10], A23.y, t1); t1 = fma2(wA[11], A45.x, t1);
            t1 = fma2(wA[12], A45.y, t1);
            acc[e] = fma2(X.y, relu2(t1), acc[e]);
        }
    }

    // ---- single-pass reduction (red aliases xs) ----
    __syncthreads();
#pragma unroll
    for (int e = 0; e < ET; e++) sm.red[(w * 32 + lane) * (ET + 1) + e] = u2f(acc[e]);
    __syncthreads();
#pragma unroll
    for (int half = 0; half < 2; half++) {
        int idx = half * 256 + tid;
        int opair = idx & 31, e = idx >> 5;
        int ee = e0 + e;
        if (ee < NE) {
            float2 s = make_float2(0.f, 0.f);
#pragma unroll
            for (int ww = 0; ww < 8; ww++) {
                float2 p = sm.red[(ww * 32 + opair) * (ET + 1) + e];
                s.x += p.x; s.y += p.y;
            }
            *(float2*)(msgout + ee * OTOT + oc + 2 * opair) = s;
        }
    }
}

// ---------------- layers 2/3 aggregate + root linear + relu ----------------
template <int L>
__global__ void __launch_bounds__(256) k_aggf(const float* __restrict__ b) {
    constexpr int OTOT = (L == 3) ? 64 : 256;
    const float* __restrict__ hin = (L == 3) ? g_h2 : g_h1;
    const float* __restrict__ lt  = (L == 3) ? g_l3t : g_l2t;
    float* __restrict__ hout      = (L == 3) ? g_h3 : g_h2;

    __shared__ float hn[256];
    __shared__ float2 sred[4][64];
    int n = blockIdx.x, o64 = threadIdx.x & 63, g = threadIdx.x >> 6;
    int oc = blockIdx.y * 64, o = oc + o64;

    hn[threadIdx.x] = hin[n * 256 + threadIdx.x];
    __syncthreads();

    int j0 = g_offs[n], j1 = g_offs[n + 1];
    float macc;
    if (L == 3) {
        macc = 0.f;
#pragma unroll
        for (int k = 0; k < 16; k++) {
            int j = j0 + g + 4 * k;
            if (j < j1) {
                int e = g_perm[j];
                macc += g_m3[0][e * 64 + o] + g_m3[1][e * 64 + o];
            }
        }
        for (int j = j0 + g + 64; j < j1; j += 4) {
            int e = g_perm[j];
            macc += g_m3[0][e * 64 + o] + g_m3[1][e * 64 + o];
        }
    } else {
        macc = gather16(g_msg, OTOT, o, j0, j1, g);
    }

    float lin = 0.f;
    int ib = g * 64;
#pragma unroll
    for (int i = 0; i < 64; i++) lin = fmaf(hn[ib + i], lt[(ib + i) * OTOT + o], lin);

    sred[g][o64] = make_float2(macc, lin);
    __syncthreads();
    if (threadIdx.x < 64) {
        float2 r0 = sred[0][threadIdx.x], r1 = sred[1][threadIdx.x];
        float2 r2 = sred[2][threadIdx.x], r3 = sred[3][threadIdx.x];
        float m = (r0.x + r1.x) + (r2.x + r3.x);
        float l = (r0.y + r1.y) + (r2.y + r3.y);
        int oo = oc + threadIdx.x;
        hout[n * OTOT + oo] = fmaxf(fmaf(m, g_invd[n], l + b[oo]), 0.f);
    }
}

// ---------------- CBT ----------------
__global__ void k_cbt(float* __restrict__ out) {
    int p = blockIdx.x, a = p / NN, bb = p % NN, c = threadIdx.x;
    float d = fabsf(g_h3[a * 64 + c] - g_h3[bb * 64 + c]) +
              fabsf(g_h3[a * 64 + c + 32] - g_h3[bb * 64 + c + 32]);
#pragma unroll
    for (int s = 16; s; s >>= 1) d += __shfl_xor_sync(0xffffffffu, d, s);
    if (c == 0) out[p] = d;
}

// ---------------- launch ----------------
extern "C" void kernel_launch(void* const* d_in, const int* in_sizes, int n_in,
                              void* d_out, int out_size) {
    const float* x   = (const float*)d_in[0];
    const float* ea  = (const float*)d_in[1];
    const int*   ei  = (const int*)d_in[2];
    const float* n1w = (const float*)d_in[3];
    const float* n1b = (const float*)d_in[4];
    const float* l1w = (const float*)d_in[5];
    const float* b1  = (const float*)d_in[6];
    const float* n2w = (const float*)d_in[7];
    const float* n2b = (const float*)d_in[8];
    const float* l2w = (const float*)d_in[9];
    const float* b2  = (const float*)d_in[10];
    const float* n3w = (const float*)d_in[11];
    const float* n3b = (const float*)d_in[12];
    const float* l3w = (const float*)d_in[13];
    const float* b3  = (const float*)d_in[14];
    float* out = (float*)d_out;
    (void)in_sizes; (void)n_in; (void)out_size;

    k_setup<<<B_ALL, 256>>>(x, ea, ei, n1w, n1b, n2w, n2b, n3w, n3b, l2w, l3w);
    k_agg1<<<dim3(NN, 4), 256>>>(x, l1w, b1);
    k_msg<2><<<dim3((NE + ET - 1) / ET, 4), 256>>>(ei);
    k_aggf<2><<<dim3(NN, 4), 256>>>(b2);
    k_msg<3><<<dim3((NE + ET - 1) / ET, 2), 256>>>(ei);
    k_aggf<3><<<dim3(NN, 1), 256>>>(b3);
    k_cbt<<<NN * NN, 32>>>(out);
}